// round 13
// baseline (speedup 1.0000x reference)
#include <cuda_runtime.h>

#define B_TOT   4096
#define T_STEPS 512
#define IN_W    4
#define H_DIM   64
#define TB      32
#define NTH     256
#define HS      36   // padded batch-row stride (floats), 16B-aligned rows

typedef unsigned long long ull;

// ---- sm_103a packed f32x2 helpers ----
__device__ __forceinline__ ull splat2(float x) {
    ull r; asm("mov.b64 %0, {%1, %1};" : "=l"(r) : "f"(x)); return r;
}
__device__ __forceinline__ ull pack2(float lo, float hi) {
    ull r; asm("mov.b64 %0, {%1, %2};" : "=l"(r) : "f"(lo), "f"(hi)); return r;
}
__device__ __forceinline__ ull fma2(ull a, ull b, ull c) {
    ull d; asm("fma.rn.f32x2 %0, %1, %2, %3;" : "=l"(d) : "l"(a), "l"(b), "l"(c)); return d;
}
__device__ __forceinline__ float2 unpack2(ull v) {
    float2 f; asm("mov.b64 {%0, %1}, %2;" : "=f"(f.x), "=f"(f.y) : "l"(v)); return f;
}

// ---- HW activations (MUFU.TANH) ----
__device__ __forceinline__ float tanhx(float x) {
    float y; asm("tanh.approx.f32 %0, %1;" : "=f"(y) : "f"(x)); return y;
}
__device__ __forceinline__ float sigx(float x) {
    return fmaf(tanhx(0.5f * x), 0.5f, 0.5f);
}

// SMEM layout (floats):
//  W1   [64][256]   @ 0      Whh0, transposed, gate-interleaved [k][j][4g]
//  W2   [128][256]  @ 16384  rows 0..63: Wih1, rows 64..127: Whh1
//  h1A  [64][HS]    @ 49152  h1 ping
//  h1B  [64][HS]    @ 51456  h1 pong
//  xbA  [4][HS]     @ 53760  x ping
//  xbB  [4][HS]     @ 53904  x pong
//  h2b  [64][HS]    @ 54048  h2 state (single buffer)
#define SM_W2   16384
#define SM_H1A  49152
#define SM_H1B2 51456
#define SM_XBA  53760
#define SM_XBB  53904
#define SM_H2B  54048
#define SM_TOT  56352   // floats = 225408 bytes

__global__ void __launch_bounds__(NTH, 1) lstm2_fused_kernel(
    const float* __restrict__ x,
    const float* __restrict__ Wih0, const float* __restrict__ Whh0,
    const float* __restrict__ bih0, const float* __restrict__ bhh0,
    const float* __restrict__ Wih1, const float* __restrict__ Whh1,
    const float* __restrict__ bih1, const float* __restrict__ bhh1,
    const float* __restrict__ Wfc,  const float* __restrict__ bfc,
    float* __restrict__ out)
{
    extern __shared__ float sm[];
    float* W1  = sm;
    float* W2  = sm + SM_W2;
    float* h2b = sm + SM_H2B;

    const int tid = threadIdx.x;
    const int j   = tid & 63;   // gate unit
    const int q   = tid >> 6;   // batch quarter (8 batches each)
    const int b0  = blockIdx.x * TB;
    const int q8  = q * 8;

    // ---- prologue: stage weights into SMEM, transposed + gate-interleaved ----
    for (int idx = tid; idx < 64 * 256; idx += NTH) {
        int k = idx >> 8, col = idx & 255;
        int r = ((col & 3) << 6) | (col >> 2);   // original gate row
        W1[idx] = Whh0[r * 64 + k];
    }
    for (int idx = tid; idx < 128 * 256; idx += NTH) {
        int k = idx >> 8, col = idx & 255;
        int r = ((col & 3) << 6) | (col >> 2);
        W2[idx] = (k < 64) ? Wih1[r * 64 + k] : Whh1[r * 64 + (k - 64)];
    }
    // zero both h1 buffers + h2; only ping buffers are read at t=0 but zero all
    for (int idx = tid; idx < 64 * HS; idx += NTH) {
        sm[SM_H1A + idx] = 0.f; sm[SM_H1B2 + idx] = 0.f; h2b[idx] = 0.f;
    }
    if (tid < TB) {
        const float4 x4 = *(const float4*)(x + ((size_t)(b0 + tid) * T_STEPS) * IN_W);
        float* xbA = sm + SM_XBA;
        xbA[0 * HS + tid] = x4.x; xbA[1 * HS + tid] = x4.y;
        xbA[2 * HS + tid] = x4.z; xbA[3 * HS + tid] = x4.w;
    }

    // per-thread constants: layer-1 input weights + fused biases (pre-splatted)
    float wx[4][4];
    ull bs1[4], bs2[4];
    #pragma unroll
    for (int gg = 0; gg < 4; gg++) {
        int r = gg * 64 + j;
        #pragma unroll
        for (int ii = 0; ii < IN_W; ii++) wx[gg][ii] = Wih0[r * IN_W + ii];
        bs1[gg] = splat2(bih0[r] + bhh0[r]);
        bs2[gg] = splat2(bih1[r] + bhh1[r]);
    }

    float c1[8], c2[8];
    #pragma unroll
    for (int i = 0; i < 8; i++) { c1[i] = 0.f; c2[i] = 0.f; }

    __syncthreads();

    const float4* W1v = (const float4*)W1;
    const float4* W2v = (const float4*)W2;

    for (int t = 0; t < T_STEPS; t++) {
        const int p   = t & 1;
        float* h1r = sm + (p ? SM_H1B2 : SM_H1A);   // read  (h1_{t-1})
        float* h1w = sm + (p ? SM_H1A  : SM_H1B2);  // write (h1_t)
        float* xbr = sm + (p ? SM_XBB  : SM_XBA);
        float* xbw = sm + (p ? SM_XBA  : SM_XBB);

        // ================= Phase A: layer-1 gates =================
        ull acc[4][4];
        #pragma unroll
        for (int gg = 0; gg < 4; gg++)
            #pragma unroll
            for (int pp = 0; pp < 4; pp++)
                acc[gg][pp] = bs1[gg];

        // x_t contribution (K=4, weights in registers)
        #pragma unroll
        for (int ii = 0; ii < IN_W; ii++) {
            ull xw0 = splat2(wx[0][ii]), xw1 = splat2(wx[1][ii]);
            ull xw2 = splat2(wx[2][ii]), xw3 = splat2(wx[3][ii]);
            const ulonglong2 xv01 = *(const ulonglong2*)(xbr + ii * HS + q8);
            const ulonglong2 xv23 = *(const ulonglong2*)(xbr + ii * HS + q8 + 4);
            ull xv[4] = { xv01.x, xv01.y, xv23.x, xv23.y };
            #pragma unroll
            for (int pp = 0; pp < 4; pp++) {
                acc[0][pp] = fma2(xv[pp], xw0, acc[0][pp]);
                acc[1][pp] = fma2(xv[pp], xw1, acc[1][pp]);
                acc[2][pp] = fma2(xv[pp], xw2, acc[2][pp]);
                acc[3][pp] = fma2(xv[pp], xw3, acc[3][pp]);
            }
        }
        // h1_{t-1} @ Whh0^T (K=64), software-pipelined: prefetch k+1 during k's FMAs
        {
            float4     w4  = W1v[j];
            ulonglong2 h01 = *(const ulonglong2*)(h1r + q8);
            ulonglong2 h23 = *(const ulonglong2*)(h1r + q8 + 4);
            #pragma unroll 8
            for (int k = 0; k < 63; k++) {
                float4     nw  = W1v[((k + 1) << 6) | j];
                ulonglong2 n01 = *(const ulonglong2*)(h1r + (k + 1) * HS + q8);
                ulonglong2 n23 = *(const ulonglong2*)(h1r + (k + 1) * HS + q8 + 4);
                ull w0 = splat2(w4.x), w1 = splat2(w4.y);
                ull w2 = splat2(w4.z), w3 = splat2(w4.w);
                ull hv[4] = { h01.x, h01.y, h23.x, h23.y };
                #pragma unroll
                for (int pp = 0; pp < 4; pp++) {
                    acc[0][pp] = fma2(hv[pp], w0, acc[0][pp]);
                    acc[1][pp] = fma2(hv[pp], w1, acc[1][pp]);
                    acc[2][pp] = fma2(hv[pp], w2, acc[2][pp]);
                    acc[3][pp] = fma2(hv[pp], w3, acc[3][pp]);
                }
                w4 = nw; h01 = n01; h23 = n23;
            }
            ull w0 = splat2(w4.x), w1 = splat2(w4.y);
            ull w2 = splat2(w4.z), w3 = splat2(w4.w);
            ull hv[4] = { h01.x, h01.y, h23.x, h23.y };
            #pragma unroll
            for (int pp = 0; pp < 4; pp++) {
                acc[0][pp] = fma2(hv[pp], w0, acc[0][pp]);
                acc[1][pp] = fma2(hv[pp], w1, acc[1][pp]);
                acc[2][pp] = fma2(hv[pp], w2, acc[2][pp]);
                acc[3][pp] = fma2(hv[pp], w3, acc[3][pp]);
            }
        }
        // no sync: A read h1r/xbr; B writes h1w/xbw (disjoint buffers)

        // ================= Phase B: layer-1 elementwise =================
        float4 xnext;
        const bool ldx = (tid < TB) && (t + 1 < T_STEPS);
        if (ldx)
            xnext = *(const float4*)(x + ((size_t)(b0 + tid) * T_STEPS + (t + 1)) * IN_W);

        #pragma unroll
        for (int pp = 0; pp < 4; pp++) {
            float2 gi = unpack2(acc[0][pp]);
            float2 gf = unpack2(acc[1][pp]);
            float2 gc = unpack2(acc[2][pp]);
            float2 go = unpack2(acc[3][pp]);
            float i0 = sigx(gi.x),  i1 = sigx(gi.y);
            float f0 = sigx(gf.x),  f1 = sigx(gf.y);
            float g0 = tanhx(gc.x), g1 = tanhx(gc.y);
            float o0 = sigx(go.x),  o1 = sigx(go.y);
            float cn0 = fmaf(f0, c1[2*pp],     i0 * g0);
            float cn1 = fmaf(f1, c1[2*pp + 1], i1 * g1);
            c1[2*pp] = cn0; c1[2*pp + 1] = cn1;
            *(ull*)(h1w + j * HS + q8 + 2 * pp) =
                pack2(o0 * tanhx(cn0), o1 * tanhx(cn1));
        }
        if (ldx) {
            xbw[0 * HS + tid] = xnext.x; xbw[1 * HS + tid] = xnext.y;
            xbw[2 * HS + tid] = xnext.z; xbw[3 * HS + tid] = xnext.w;
        }
        __syncthreads();   // sync2: h1w (h1_t) + xbw ready for C / next A

        // ===== Phase C: layer-2 gates, K=128 ([h1_t ; h2_{t-1}]) =====
        #pragma unroll
        for (int gg = 0; gg < 4; gg++)
            #pragma unroll
            for (int pp = 0; pp < 4; pp++)
                acc[gg][pp] = bs2[gg];

        {   // part 1: h1_t rows, W2 rows 0..63 — software-pipelined
            float4     w4  = W2v[j];
            ulonglong2 h01 = *(const ulonglong2*)(h1w + q8);
            ulonglong2 h23 = *(const ulonglong2*)(h1w + q8 + 4);
            #pragma unroll 8
            for (int k = 0; k < 64; k++) {
                // prefetch: next within part1, else first of part2 (h2b)
                float4     nw;
                ulonglong2 n01, n23;
                if (k < 63) {
                    nw  = W2v[((k + 1) << 6) | j];
                    n01 = *(const ulonglong2*)(h1w + (k + 1) * HS + q8);
                    n23 = *(const ulonglong2*)(h1w + (k + 1) * HS + q8 + 4);
                } else {
                    nw  = W2v[(64 << 6) | j];
                    n01 = *(const ulonglong2*)(h2b + q8);
                    n23 = *(const ulonglong2*)(h2b + q8 + 4);
                }
                ull w0 = splat2(w4.x), w1 = splat2(w4.y);
                ull w2 = splat2(w4.z), w3 = splat2(w4.w);
                ull hv[4] = { h01.x, h01.y, h23.x, h23.y };
                #pragma unroll
                for (int pp = 0; pp < 4; pp++) {
                    acc[0][pp] = fma2(hv[pp], w0, acc[0][pp]);
                    acc[1][pp] = fma2(hv[pp], w1, acc[1][pp]);
                    acc[2][pp] = fma2(hv[pp], w2, acc[2][pp]);
                    acc[3][pp] = fma2(hv[pp], w3, acc[3][pp]);
                }
                w4 = nw; h01 = n01; h23 = n23;
            }
            // part 2: h2_{t-1} rows, W2 rows 64..127
            #pragma unroll 8
            for (int k = 0; k < 63; k++) {
                float4     nw  = W2v[((65 + k) << 6) | j];
                ulonglong2 n01 = *(const ulonglong2*)(h2b + (k + 1) * HS + q8);
                ulonglong2 n23 = *(const ulonglong2*)(h2b + (k + 1) * HS + q8 + 4);
                ull w0 = splat2(w4.x), w1 = splat2(w4.y);
                ull w2 = splat2(w4.z), w3 = splat2(w4.w);
                ull hv[4] = { h01.x, h01.y, h23.x, h23.y };
                #pragma unroll
                for (int pp = 0; pp < 4; pp++) {
                    acc[0][pp] = fma2(hv[pp], w0, acc[0][pp]);
                    acc[1][pp] = fma2(hv[pp], w1, acc[1][pp]);
                    acc[2][pp] = fma2(hv[pp], w2, acc[2][pp]);
                    acc[3][pp] = fma2(hv[pp], w3, acc[3][pp]);
                }
                w4 = nw; h01 = n01; h23 = n23;
            }
            ull w0 = splat2(w4.x), w1 = splat2(w4.y);
            ull w2 = splat2(w4.z), w3 = splat2(w4.w);
            ull hv[4] = { h01.x, h01.y, h23.x, h23.y };
            #pragma unroll
            for (int pp = 0; pp < 4; pp++) {
                acc[0][pp] = fma2(hv[pp], w0, acc[0][pp]);
                acc[1][pp] = fma2(hv[pp], w1, acc[1][pp]);
                acc[2][pp] = fma2(hv[pp], w2, acc[2][pp]);
                acc[3][pp] = fma2(hv[pp], w3, acc[3][pp]);
            }
        }
        __syncthreads();   // sync3: all reads of h2b done before D overwrites

        // ================= Phase D: layer-2 elementwise =================
        #pragma unroll
        for (int pp = 0; pp < 4; pp++) {
            float2 gi = unpack2(acc[0][pp]);
            float2 gf = unpack2(acc[1][pp]);
            float2 gc = unpack2(acc[2][pp]);
            float2 go = unpack2(acc[3][pp]);
            float i0 = sigx(gi.x),  i1 = sigx(gi.y);
            float f0 = sigx(gf.x),  f1 = sigx(gf.y);
            float g0 = tanhx(gc.x), g1 = tanhx(gc.y);
            float o0 = sigx(go.x),  o1 = sigx(go.y);
            float cn0 = fmaf(f0, c2[2*pp],     i0 * g0);
            float cn1 = fmaf(f1, c2[2*pp + 1], i1 * g1);
            c2[2*pp] = cn0; c2[2*pp + 1] = cn1;
            *(ull*)(h2b + j * HS + q8 + 2 * pp) =
                pack2(o0 * tanhx(cn0), o1 * tanhx(cn1));
        }
        // no sync: next Phase A reads h1/xb buffers only; D->C' ordered by sync2'
    }
    __syncthreads();

    // ================= FC head: out[b] = h2_final @ Wfc^T + bfc =================
    for (int tt = tid; tt < TB * 20; tt += NTH) {
        int bb = tt / 20, o = tt % 20;
        float s = bfc[o];
        #pragma unroll 8
        for (int jj = 0; jj < 64; jj++)
            s += h2b[jj * HS + bb] * Wfc[o * 64 + jj];
        out[(size_t)(b0 + bb) * 20 + o] = s;
    }
}

extern "C" void kernel_launch(void* const* d_in, const int* in_sizes, int n_in,
                              void* d_out, int out_size) {
    const float* x    = (const float*)d_in[0];
    const float* Wih0 = (const float*)d_in[1];
    const float* Whh0 = (const float*)d_in[2];
    const float* bih0 = (const float*)d_in[3];
    const float* bhh0 = (const float*)d_in[4];
    const float* Wih1 = (const float*)d_in[5];
    const float* Whh1 = (const float*)d_in[6];
    const float* bih1 = (const float*)d_in[7];
    const float* bhh1 = (const float*)d_in[8];
    const float* Wfc  = (const float*)d_in[9];
    const float* bfc  = (const float*)d_in[10];
    float* out = (float*)d_out;

    const size_t smem = (size_t)SM_TOT * sizeof(float);
    cudaFuncSetAttribute(lstm2_fused_kernel,
                         cudaFuncAttributeMaxDynamicSharedMemorySize, (int)smem);
    lstm2_fused_kernel<<<B_TOT / TB, NTH, smem>>>(
        x, Wih0, Whh0, bih0, bhh0, Wih1, Whh1, bih1, bhh1, Wfc, bfc, out);
}

// round 16
// speedup vs baseline: 1.2034x; 1.2034x over previous
#include <cuda_runtime.h>

#define B_TOT   4096
#define T_STEPS 512
#define IN_W    4
#define H_DIM   64
#define TB      32
#define NTH     256
#define HS      36   // xb row stride (floats)
#define HD      68   // duplicated-h row stride (floats): 64 dup floats + 4 pad, 16B-aligned

typedef unsigned long long ull;

// ---- sm_103a packed f32x2 helpers ----
__device__ __forceinline__ ull splat2(float x) {
    ull r; asm("mov.b64 %0, {%1, %1};" : "=l"(r) : "f"(x)); return r;
}
__device__ __forceinline__ ull pack2(float lo, float hi) {
    ull r; asm("mov.b64 %0, {%1, %2};" : "=l"(r) : "f"(lo), "f"(hi)); return r;
}
__device__ __forceinline__ ull fma2(ull a, ull b, ull c) {
    ull d; asm("fma.rn.f32x2 %0, %1, %2, %3;" : "=l"(d) : "l"(a), "l"(b), "l"(c)); return d;
}
__device__ __forceinline__ float2 unpack2(ull v) {
    float2 f; asm("mov.b64 {%0, %1}, %2;" : "=f"(f.x), "=f"(f.y) : "l"(v)); return f;
}

// ---- HW activations (MUFU.TANH) ----
__device__ __forceinline__ float tanhx(float x) {
    float y; asm("tanh.approx.f32 %0, %1;" : "=f"(y) : "f"(x)); return y;
}
__device__ __forceinline__ float sigx(float x) {
    return fmaf(tanhx(0.5f * x), 0.5f, 0.5f);
}

// SMEM layout (floats):
//  W1   [64][256]   @ 0      Whh0, transposed, gate-interleaved [k][j][i,f,g,o]
//  W2   [128][256]  @ 16384  rows 0..63: Wih1, rows 64..127: Whh1 (same interleave)
//  h1d  [64][HD]    @ 49152  h1 state, DUPLICATED pairs: row k = (h[k][b],h[k][b]) b=0..31
//  h2d  [64][HD]    @ 53504  h2 state, duplicated pairs
//  xb   [4][HS]     @ 57856  x_t [feature][batch] (not duplicated)
#define SM_W2   16384
#define SM_H1D  49152
#define SM_H2D  53504
#define SM_XB   57856
#define SM_TOT  58000   // floats = 232000 bytes (<= 232448 max)

__global__ void __launch_bounds__(NTH, 1) lstm2_fused_kernel(
    const float* __restrict__ x,
    const float* __restrict__ Wih0, const float* __restrict__ Whh0,
    const float* __restrict__ bih0, const float* __restrict__ bhh0,
    const float* __restrict__ Wih1, const float* __restrict__ Whh1,
    const float* __restrict__ bih1, const float* __restrict__ bhh1,
    const float* __restrict__ Wfc,  const float* __restrict__ bfc,
    float* __restrict__ out)
{
    extern __shared__ float sm[];
    float* W1  = sm;
    float* W2  = sm + SM_W2;
    float* h1d = sm + SM_H1D;
    float* h2d = sm + SM_H2D;
    float* xb  = sm + SM_XB;

    const int tid = threadIdx.x;
    const int j   = tid & 63;        // gate unit
    const int q   = tid >> 6;        // batch quarter (8 batches each)
    const int b0  = blockIdx.x * TB;
    const int q8  = q * 8;           // batch offset (scalar arrays)
    const int q16 = q * 16;          // column offset in duplicated rows

    // ---- prologue: stage weights into SMEM, transposed + gate-interleaved ----
    // col = j*4 + g  maps to original gate row r = g*64 + j
    for (int idx = tid; idx < 64 * 256; idx += NTH) {
        int k = idx >> 8, col = idx & 255;
        int r = ((col & 3) << 6) | (col >> 2);
        W1[idx] = Whh0[r * 64 + k];
    }
    for (int idx = tid; idx < 128 * 256; idx += NTH) {
        int k = idx >> 8, col = idx & 255;
        int r = ((col & 3) << 6) | (col >> 2);
        W2[idx] = (k < 64) ? Wih1[r * 64 + k] : Whh1[r * 64 + (k - 64)];
    }
    for (int idx = tid; idx < 64 * HD; idx += NTH) { h1d[idx] = 0.f; h2d[idx] = 0.f; }
    if (tid < TB) {
        const float4 x4 = *(const float4*)(x + ((size_t)(b0 + tid) * T_STEPS) * IN_W);
        xb[0 * HS + tid] = x4.x; xb[1 * HS + tid] = x4.y;
        xb[2 * HS + tid] = x4.z; xb[3 * HS + tid] = x4.w;
    }

    // per-thread constants: layer-1 input weights + fused biases, packed as
    // gate-pairs: _if = (gate_i, gate_f), _go = (gate_g, gate_o)
    ull wx_if[IN_W], wx_go[IN_W];
    #pragma unroll
    for (int ii = 0; ii < IN_W; ii++) {
        wx_if[ii] = pack2(Wih0[(0 * 64 + j) * IN_W + ii], Wih0[(1 * 64 + j) * IN_W + ii]);
        wx_go[ii] = pack2(Wih0[(2 * 64 + j) * IN_W + ii], Wih0[(3 * 64 + j) * IN_W + ii]);
    }
    const ull bs1_if = pack2(bih0[0*64+j] + bhh0[0*64+j], bih0[1*64+j] + bhh0[1*64+j]);
    const ull bs1_go = pack2(bih0[2*64+j] + bhh0[2*64+j], bih0[3*64+j] + bhh0[3*64+j]);
    const ull bs2_if = pack2(bih1[0*64+j] + bhh1[0*64+j], bih1[1*64+j] + bhh1[1*64+j]);
    const ull bs2_go = pack2(bih1[2*64+j] + bhh1[2*64+j], bih1[3*64+j] + bhh1[3*64+j]);

    float c1[8], c2[8];
    #pragma unroll
    for (int i = 0; i < 8; i++) { c1[i] = 0.f; c2[i] = 0.f; }

    __syncthreads();

    for (int t = 0; t < T_STEPS; t++) {
        // ================= Phase A: layer-1 gates =================
        // acc_if[b] = (pre_i, pre_f) for batch b; acc_go[b] = (pre_g, pre_o)
        ull acc_if[8], acc_go[8];
        #pragma unroll
        for (int b = 0; b < 8; b++) { acc_if[b] = bs1_if; acc_go[b] = bs1_go; }

        // x_t contribution (K=4): x values splatted (only 4 iters, cost is small)
        #pragma unroll
        for (int ii = 0; ii < IN_W; ii++) {
            float4 xa = *(const float4*)(xb + ii * HS + q8);
            float4 xbv = *(const float4*)(xb + ii * HS + q8 + 4);
            float xf[8] = { xa.x, xa.y, xa.z, xa.w, xbv.x, xbv.y, xbv.z, xbv.w };
            #pragma unroll
            for (int b = 0; b < 8; b++) {
                ull sp = splat2(xf[b]);
                acc_if[b] = fma2(sp, wx_if[ii], acc_if[b]);
                acc_go[b] = fma2(sp, wx_go[ii], acc_go[b]);
            }
        }
        // h1_{t-1} @ Whh0^T (K=64): weights packed in SMEM, h pre-duplicated
        #pragma unroll 4
        for (int k = 0; k < 64; k++) {
            ulonglong2 wv = *(const ulonglong2*)(W1 + k * 256 + j * 4);  // (wi,wf),(wg,wo)
            ulonglong2 h01 = *(const ulonglong2*)(h1d + k * HD + q16);
            ulonglong2 h23 = *(const ulonglong2*)(h1d + k * HD + q16 + 4);
            ulonglong2 h45 = *(const ulonglong2*)(h1d + k * HD + q16 + 8);
            ulonglong2 h67 = *(const ulonglong2*)(h1d + k * HD + q16 + 12);
            ull hv[8] = { h01.x, h01.y, h23.x, h23.y, h45.x, h45.y, h67.x, h67.y };
            #pragma unroll
            for (int b = 0; b < 8; b++) {
                acc_if[b] = fma2(hv[b], wv.x, acc_if[b]);
                acc_go[b] = fma2(hv[b], wv.y, acc_go[b]);
            }
        }
        __syncthreads();   // sync1: all threads done reading h1d/xb

        // ================= Phase B: layer-1 elementwise =================
        float4 xnext;
        const bool ldx = (tid < TB) && (t + 1 < T_STEPS);
        if (ldx)
            xnext = *(const float4*)(x + ((size_t)(b0 + tid) * T_STEPS + (t + 1)) * IN_W);

        {
            float hout[8];
            #pragma unroll
            for (int b = 0; b < 8; b++) {
                float2 gif = unpack2(acc_if[b]);
                float2 ggo = unpack2(acc_go[b]);
                float iv = sigx(gif.x), fv = sigx(gif.y);
                float gv = tanhx(ggo.x), ov = sigx(ggo.y);
                float cn = fmaf(fv, c1[b], iv * gv);
                c1[b] = cn;
                hout[b] = ov * tanhx(cn);
            }
            #pragma unroll
            for (int b = 0; b < 8; b += 2) {
                ulonglong2 st;
                st.x = splat2(hout[b]);
                st.y = splat2(hout[b + 1]);
                *(ulonglong2*)(h1d + j * HD + q16 + 2 * b) = st;
            }
        }
        if (ldx) {
            xb[0 * HS + tid] = xnext.x; xb[1 * HS + tid] = xnext.y;
            xb[2 * HS + tid] = xnext.z; xb[3 * HS + tid] = xnext.w;
        }
        __syncthreads();   // sync2: h1d (h1_t) ready for layer 2

        // ===== Phase C: layer-2 gates, K=128 ([h1_t ; h2_{t-1}]) =====
        #pragma unroll
        for (int b = 0; b < 8; b++) { acc_if[b] = bs2_if; acc_go[b] = bs2_go; }

        #pragma unroll 4
        for (int k = 0; k < 64; k++) {
            ulonglong2 wv = *(const ulonglong2*)(W2 + k * 256 + j * 4);
            ulonglong2 h01 = *(const ulonglong2*)(h1d + k * HD + q16);
            ulonglong2 h23 = *(const ulonglong2*)(h1d + k * HD + q16 + 4);
            ulonglong2 h45 = *(const ulonglong2*)(h1d + k * HD + q16 + 8);
            ulonglong2 h67 = *(const ulonglong2*)(h1d + k * HD + q16 + 12);
            ull hv[8] = { h01.x, h01.y, h23.x, h23.y, h45.x, h45.y, h67.x, h67.y };
            #pragma unroll
            for (int b = 0; b < 8; b++) {
                acc_if[b] = fma2(hv[b], wv.x, acc_if[b]);
                acc_go[b] = fma2(hv[b], wv.y, acc_go[b]);
            }
        }
        #pragma unroll 4
        for (int k = 0; k < 64; k++) {
            ulonglong2 wv = *(const ulonglong2*)(W2 + (64 + k) * 256 + j * 4);
            ulonglong2 h01 = *(const ulonglong2*)(h2d + k * HD + q16);
            ulonglong2 h23 = *(const ulonglong2*)(h2d + k * HD + q16 + 4);
            ulonglong2 h45 = *(const ulonglong2*)(h2d + k * HD + q16 + 8);
            ulonglong2 h67 = *(const ulonglong2*)(h2d + k * HD + q16 + 12);
            ull hv[8] = { h01.x, h01.y, h23.x, h23.y, h45.x, h45.y, h67.x, h67.y };
            #pragma unroll
            for (int b = 0; b < 8; b++) {
                acc_if[b] = fma2(hv[b], wv.x, acc_if[b]);
                acc_go[b] = fma2(hv[b], wv.y, acc_go[b]);
            }
        }
        __syncthreads();   // sync3: all threads done reading h2d before D overwrites

        // ================= Phase D: layer-2 elementwise =================
        {
            float hout[8];
            #pragma unroll
            for (int b = 0; b < 8; b++) {
                float2 gif = unpack2(acc_if[b]);
                float2 ggo = unpack2(acc_go[b]);
                float iv = sigx(gif.x), fv = sigx(gif.y);
                float gv = tanhx(ggo.x), ov = sigx(ggo.y);
                float cn = fmaf(fv, c2[b], iv * gv);
                c2[b] = cn;
                hout[b] = ov * tanhx(cn);
            }
            #pragma unroll
            for (int b = 0; b < 8; b += 2) {
                ulonglong2 st;
                st.x = splat2(hout[b]);
                st.y = splat2(hout[b + 1]);
                *(ulonglong2*)(h2d + j * HD + q16 + 2 * b) = st;
            }
        }
        // no sync: next Phase A reads h1d/xb only; D->C' ordered by sync1'+sync2'
    }
    __syncthreads();

    // ================= FC head: out[b] = h2_final @ Wfc^T + bfc =================
    for (int tt = tid; tt < TB * 20; tt += NTH) {
        int bb = tt / 20, o = tt % 20;
        float s = bfc[o];
        #pragma unroll 8
        for (int jj = 0; jj < 64; jj++)
            s += h2d[jj * HD + 2 * bb] * Wfc[o * 64 + jj];
        out[(size_t)(b0 + bb) * 20 + o] = s;
    }
}

extern "C" void kernel_launch(void* const* d_in, const int* in_sizes, int n_in,
                              void* d_out, int out_size) {
    const float* x    = (const float*)d_in[0];
    const float* Wih0 = (const float*)d_in[1];
    const float* Whh0 = (const float*)d_in[2];
    const float* bih0 = (const float*)d_in[3];
    const float* bhh0 = (const float*)d_in[4];
    const float* Wih1 = (const float*)d_in[5];
    const float* Whh1 = (const float*)d_in[6];
    const float* bih1 = (const float*)d_in[7];
    const float* bhh1 = (const float*)d_in[8];
    const float* Wfc  = (const float*)d_in[9];
    const float* bfc  = (const float*)d_in[10];
    float* out = (float*)d_out;

    const size_t smem = (size_t)SM_TOT * sizeof(float);
    cudaFuncSetAttribute(lstm2_fused_kernel,
                         cudaFuncAttributeMaxDynamicSharedMemorySize, (int)smem);
    lstm2_fused_kernel<<<B_TOT / TB, NTH, smem>>>(
        x, Wih0, Whh0, bih0, bhh0, Wih1, Whh1, bih1, bhh1, Wfc, bfc, out);
}

// round 17
// speedup vs baseline: 1.4940x; 1.2415x over previous
#include <cuda_runtime.h>

#define B_TOT   4096
#define T_STEPS 512
#define IN_W    4
#define H_DIM   64
#define TB      32
#define NTH     256
#define HS      36   // padded batch-row stride (floats), 16B-aligned rows

typedef unsigned long long ull;

// ---- sm_103a packed f32x2 helpers ----
__device__ __forceinline__ ull splat2(float x) {
    ull r; asm("mov.b64 %0, {%1, %1};" : "=l"(r) : "f"(x)); return r;
}
__device__ __forceinline__ ull pack2(float lo, float hi) {
    ull r; asm("mov.b64 %0, {%1, %2};" : "=l"(r) : "f"(lo), "f"(hi)); return r;
}
__device__ __forceinline__ ull fma2(ull a, ull b, ull c) {
    ull d; asm("fma.rn.f32x2 %0, %1, %2, %3;" : "=l"(d) : "l"(a), "l"(b), "l"(c)); return d;
}
__device__ __forceinline__ float2 unpack2(ull v) {
    float2 f; asm("mov.b64 {%0, %1}, %2;" : "=f"(f.x), "=f"(f.y) : "l"(v)); return f;
}

// ---- HW activations (MUFU.TANH) ----
__device__ __forceinline__ float tanhx(float x) {
    float y; asm("tanh.approx.f32 %0, %1;" : "=f"(y) : "f"(x)); return y;
}
__device__ __forceinline__ float sigx(float x) {
    return fmaf(tanhx(0.5f * x), 0.5f, 0.5f);
}

// SMEM layout (floats) — identical to the 4480us R11 kernel:
//  W1   [64][256]  @ 0       Whh0, transposed, gate-interleaved [k][j][4g]
//  W2   [128][256] @ 16384   rows 0..63: Wih1, rows 64..127: Whh1
//  h1b  [64][HS]   @ 49152   h1 state [unit][batch]
//  h2b  [64][HS]   @ 51456   h2 state
//  xb   [4][HS]    @ 53760   x_t [feature][batch]
#define SM_W2   16384
#define SM_H1B  49152
#define SM_H2B  51456
#define SM_XB   53760
#define SM_TOT  53904   // floats = 215616 bytes

__global__ void __launch_bounds__(NTH, 1) lstm2_fused_kernel(
    const float* __restrict__ x,
    const float* __restrict__ Wih0, const float* __restrict__ Whh0,
    const float* __restrict__ bih0, const float* __restrict__ bhh0,
    const float* __restrict__ Wih1, const float* __restrict__ Whh1,
    const float* __restrict__ bih1, const float* __restrict__ bhh1,
    const float* __restrict__ Wfc,  const float* __restrict__ bfc,
    float* __restrict__ out)
{
    extern __shared__ float sm[];
    float* W1  = sm;
    float* W2  = sm + SM_W2;
    float* h1b = sm + SM_H1B;
    float* h2b = sm + SM_H2B;
    float* xb  = sm + SM_XB;

    const int tid = threadIdx.x;
    const int j   = tid & 63;   // gate unit
    const int q   = tid >> 6;   // batch quarter (8 batches each)
    const int b0  = blockIdx.x * TB;
    const int q8  = q * 8;

    // ---- prologue: stage weights into SMEM, transposed + gate-interleaved ----
    for (int idx = tid; idx < 64 * 256; idx += NTH) {
        int k = idx >> 8, col = idx & 255;
        int r = ((col & 3) << 6) | (col >> 2);   // original gate row
        W1[idx] = Whh0[r * 64 + k];
    }
    for (int idx = tid; idx < 128 * 256; idx += NTH) {
        int k = idx >> 8, col = idx & 255;
        int r = ((col & 3) << 6) | (col >> 2);
        W2[idx] = (k < 64) ? Wih1[r * 64 + k] : Whh1[r * 64 + (k - 64)];
    }
    for (int idx = tid; idx < 64 * HS; idx += NTH) { h1b[idx] = 0.f; h2b[idx] = 0.f; }
    if (tid < TB) {
        const float4 x4 = *(const float4*)(x + ((size_t)(b0 + tid) * T_STEPS) * IN_W);
        xb[0 * HS + tid] = x4.x; xb[1 * HS + tid] = x4.y;
        xb[2 * HS + tid] = x4.z; xb[3 * HS + tid] = x4.w;
    }

    // per-thread constants: layer-1 input weights + fused biases (pre-splatted)
    float wx[4][4];
    ull bs1[4], bs2[4];
    #pragma unroll
    for (int gg = 0; gg < 4; gg++) {
        int r = gg * 64 + j;
        #pragma unroll
        for (int ii = 0; ii < IN_W; ii++) wx[gg][ii] = Wih0[r * IN_W + ii];
        bs1[gg] = splat2(bih0[r] + bhh0[r]);
        bs2[gg] = splat2(bih1[r] + bhh1[r]);
    }

    float c1[8], c2[8];
    #pragma unroll
    for (int i = 0; i < 8; i++) { c1[i] = 0.f; c2[i] = 0.f; }

    __syncthreads();

    const float4* W1v = (const float4*)W1;
    const float4* W2v = (const float4*)W2;

    // persistent accumulators (live across barriers)
    ull acc1[4][4];   // layer-1 gate preactivations
    ull acc2[4][4];   // layer-2 gate preactivations

    // ================= A(0): layer-1 gates for t=0 (not fused) =================
    #pragma unroll
    for (int gg = 0; gg < 4; gg++)
        #pragma unroll
        for (int pp = 0; pp < 4; pp++)
            acc1[gg][pp] = bs1[gg];
    #pragma unroll
    for (int ii = 0; ii < IN_W; ii++) {
        ull xw0 = splat2(wx[0][ii]), xw1 = splat2(wx[1][ii]);
        ull xw2 = splat2(wx[2][ii]), xw3 = splat2(wx[3][ii]);
        const ulonglong2 xv01 = *(const ulonglong2*)(xb + ii * HS + q8);
        const ulonglong2 xv23 = *(const ulonglong2*)(xb + ii * HS + q8 + 4);
        ull xv[4] = { xv01.x, xv01.y, xv23.x, xv23.y };
        #pragma unroll
        for (int pp = 0; pp < 4; pp++) {
            acc1[0][pp] = fma2(xv[pp], xw0, acc1[0][pp]);
            acc1[1][pp] = fma2(xv[pp], xw1, acc1[1][pp]);
            acc1[2][pp] = fma2(xv[pp], xw2, acc1[2][pp]);
            acc1[3][pp] = fma2(xv[pp], xw3, acc1[3][pp]);
        }
    }
    #pragma unroll 4
    for (int k = 0; k < 64; k++) {
        float4 w4 = W1v[(k << 6) | j];
        const ulonglong2 h01 = *(const ulonglong2*)(h1b + k * HS + q8);
        const ulonglong2 h23 = *(const ulonglong2*)(h1b + k * HS + q8 + 4);
        ull w0 = splat2(w4.x), w1 = splat2(w4.y);
        ull w2 = splat2(w4.z), w3 = splat2(w4.w);
        ull hv[4] = { h01.x, h01.y, h23.x, h23.y };
        #pragma unroll
        for (int pp = 0; pp < 4; pp++) {
            acc1[0][pp] = fma2(hv[pp], w0, acc1[0][pp]);
            acc1[1][pp] = fma2(hv[pp], w1, acc1[1][pp]);
            acc1[2][pp] = fma2(hv[pp], w2, acc1[2][pp]);
            acc1[3][pp] = fma2(hv[pp], w3, acc1[3][pp]);
        }
    }

    for (int t = 0; t < T_STEPS; t++) {
        __syncthreads();   // sync1: A(t) reads of h1b/xb done (and D(t-1) h2b stores done)

        // ========= R2: B(t) elementwise  ⊗  C2(t) (h2_{t-1} rows, W2 rows 64..127) =========
        #pragma unroll
        for (int gg = 0; gg < 4; gg++)
            #pragma unroll
            for (int pp = 0; pp < 4; pp++)
                acc2[gg][pp] = bs2[gg];

        float4 xnext;
        const bool ldx = (tid < TB) && (t + 1 < T_STEPS);
        if (ldx)
            xnext = *(const float4*)(x + ((size_t)(b0 + tid) * T_STEPS + (t + 1)) * IN_W);

        #pragma unroll
        for (int pp = 0; pp < 4; pp++) {
            // ---- B: cell pair pp (MUFU work, interleaves with C2 FMAs below) ----
            {
                float2 gi = unpack2(acc1[0][pp]);
                float2 gf = unpack2(acc1[1][pp]);
                float2 gc = unpack2(acc1[2][pp]);
                float2 go = unpack2(acc1[3][pp]);
                float i0 = sigx(gi.x),  i1 = sigx(gi.y);
                float f0 = sigx(gf.x),  f1 = sigx(gf.y);
                float g0 = tanhx(gc.x), g1 = tanhx(gc.y);
                float o0 = sigx(go.x),  o1 = sigx(go.y);
                float cn0 = fmaf(f0, c1[2*pp],     i0 * g0);
                float cn1 = fmaf(f1, c1[2*pp + 1], i1 * g1);
                c1[2*pp] = cn0; c1[2*pp + 1] = cn1;
                *(ull*)(h1b + j * HS + q8 + 2 * pp) =
                    pack2(o0 * tanhx(cn0), o1 * tanhx(cn1));
            }
            // ---- C2: 16 k-iters (FMA work) ----
            #pragma unroll 4
            for (int k = 16 * pp; k < 16 * pp + 16; k++) {
                float4 w4 = W2v[((64 + k) << 6) | j];
                const ulonglong2 h01 = *(const ulonglong2*)(h2b + k * HS + q8);
                const ulonglong2 h23 = *(const ulonglong2*)(h2b + k * HS + q8 + 4);
                ull w0 = splat2(w4.x), w1 = splat2(w4.y);
                ull w2 = splat2(w4.z), w3 = splat2(w4.w);
                ull hv[4] = { h01.x, h01.y, h23.x, h23.y };
                #pragma unroll
                for (int u = 0; u < 4; u++) {
                    acc2[0][u] = fma2(hv[u], w0, acc2[0][u]);
                    acc2[1][u] = fma2(hv[u], w1, acc2[1][u]);
                    acc2[2][u] = fma2(hv[u], w2, acc2[2][u]);
                    acc2[3][u] = fma2(hv[u], w3, acc2[3][u]);
                }
            }
        }
        if (ldx) {
            xb[0 * HS + tid] = xnext.x; xb[1 * HS + tid] = xnext.y;
            xb[2 * HS + tid] = xnext.z; xb[3 * HS + tid] = xnext.w;
        }
        __syncthreads();   // sync2: h1b (h1_t) + xb(t+1) ready

        // ========= R3: C1(t) — h1_t rows, W2 rows 0..63 =========
        #pragma unroll 4
        for (int k = 0; k < 64; k++) {
            float4 w4 = W2v[(k << 6) | j];
            const ulonglong2 h01 = *(const ulonglong2*)(h1b + k * HS + q8);
            const ulonglong2 h23 = *(const ulonglong2*)(h1b + k * HS + q8 + 4);
            ull w0 = splat2(w4.x), w1 = splat2(w4.y);
            ull w2 = splat2(w4.z), w3 = splat2(w4.w);
            ull hv[4] = { h01.x, h01.y, h23.x, h23.y };
            #pragma unroll
            for (int pp = 0; pp < 4; pp++) {
                acc2[0][pp] = fma2(hv[pp], w0, acc2[0][pp]);
                acc2[1][pp] = fma2(hv[pp], w1, acc2[1][pp]);
                acc2[2][pp] = fma2(hv[pp], w2, acc2[2][pp]);
                acc2[3][pp] = fma2(hv[pp], w3, acc2[3][pp]);
            }
        }
        __syncthreads();   // sync3: C1 reads done; h2b reads (C2) long done

        if (t + 1 < T_STEPS) {
            // ========= R1: A(t+1)  ⊗  D(t) elementwise =========
            #pragma unroll
            for (int gg = 0; gg < 4; gg++)
                #pragma unroll
                for (int pp = 0; pp < 4; pp++)
                    acc1[gg][pp] = bs1[gg];
            // x(t+1) contribution (K=4)
            #pragma unroll
            for (int ii = 0; ii < IN_W; ii++) {
                ull xw0 = splat2(wx[0][ii]), xw1 = splat2(wx[1][ii]);
                ull xw2 = splat2(wx[2][ii]), xw3 = splat2(wx[3][ii]);
                const ulonglong2 xv01 = *(const ulonglong2*)(xb + ii * HS + q8);
                const ulonglong2 xv23 = *(const ulonglong2*)(xb + ii * HS + q8 + 4);
                ull xv[4] = { xv01.x, xv01.y, xv23.x, xv23.y };
                #pragma unroll
                for (int pp = 0; pp < 4; pp++) {
                    acc1[0][pp] = fma2(xv[pp], xw0, acc1[0][pp]);
                    acc1[1][pp] = fma2(xv[pp], xw1, acc1[1][pp]);
                    acc1[2][pp] = fma2(xv[pp], xw2, acc1[2][pp]);
                    acc1[3][pp] = fma2(xv[pp], xw3, acc1[3][pp]);
                }
            }
            #pragma unroll
            for (int pp = 0; pp < 4; pp++) {
                // ---- D: cell pair pp (MUFU, interleaves with A FMAs below) ----
                {
                    float2 gi = unpack2(acc2[0][pp]);
                    float2 gf = unpack2(acc2[1][pp]);
                    float2 gc = unpack2(acc2[2][pp]);
                    float2 go = unpack2(acc2[3][pp]);
                    float i0 = sigx(gi.x),  i1 = sigx(gi.y);
                    float f0 = sigx(gf.x),  f1 = sigx(gf.y);
                    float g0 = tanhx(gc.x), g1 = tanhx(gc.y);
                    float o0 = sigx(go.x),  o1 = sigx(go.y);
                    float cn0 = fmaf(f0, c2[2*pp],     i0 * g0);
                    float cn1 = fmaf(f1, c2[2*pp + 1], i1 * g1);
                    c2[2*pp] = cn0; c2[2*pp + 1] = cn1;
                    *(ull*)(h2b + j * HS + q8 + 2 * pp) =
                        pack2(o0 * tanhx(cn0), o1 * tanhx(cn1));
                }
                // ---- A: 16 k-iters over h1_t (stable until B(t+1) after sync1) ----
                #pragma unroll 4
                for (int k = 16 * pp; k < 16 * pp + 16; k++) {
                    float4 w4 = W1v[(k << 6) | j];
                    const ulonglong2 h01 = *(const ulonglong2*)(h1b + k * HS + q8);
                    const ulonglong2 h23 = *(const ulonglong2*)(h1b + k * HS + q8 + 4);
                    ull w0 = splat2(w4.x), w1 = splat2(w4.y);
                    ull w2 = splat2(w4.z), w3 = splat2(w4.w);
                    ull hv[4] = { h01.x, h01.y, h23.x, h23.y };
                    #pragma unroll
                    for (int u = 0; u < 4; u++) {
                        acc1[0][u] = fma2(hv[u], w0, acc1[0][u]);
                        acc1[1][u] = fma2(hv[u], w1, acc1[1][u]);
                        acc1[2][u] = fma2(hv[u], w2, acc1[2][u]);
                        acc1[3][u] = fma2(hv[u], w3, acc1[3][u]);
                    }
                }
            }
        } else {
            // ========= final D(T-1) standalone =========
            #pragma unroll
            for (int pp = 0; pp < 4; pp++) {
                float2 gi = unpack2(acc2[0][pp]);
                float2 gf = unpack2(acc2[1][pp]);
                float2 gc = unpack2(acc2[2][pp]);
                float2 go = unpack2(acc2[3][pp]);
                float i0 = sigx(gi.x),  i1 = sigx(gi.y);
                float f0 = sigx(gf.x),  f1 = sigx(gf.y);
                float g0 = tanhx(gc.x), g1 = tanhx(gc.y);
                float o0 = sigx(go.x),  o1 = sigx(go.y);
                float cn0 = fmaf(f0, c2[2*pp],     i0 * g0);
                float cn1 = fmaf(f1, c2[2*pp + 1], i1 * g1);
                c2[2*pp] = cn0; c2[2*pp + 1] = cn1;
                *(ull*)(h2b + j * HS + q8 + 2 * pp) =
                    pack2(o0 * tanhx(cn0), o1 * tanhx(cn1));
            }
        }
    }
    __syncthreads();

    // ================= FC head: out[b] = h2_final @ Wfc^T + bfc =================
    for (int tt = tid; tt < TB * 20; tt += NTH) {
        int bb = tt / 20, o = tt % 20;
        float s = bfc[o];
        #pragma unroll 8
        for (int jj = 0; jj < 64; jj++)
            s += h2b[jj * HS + bb] * Wfc[o * 64 + jj];
        out[(size_t)(b0 + bb) * 20 + o] = s;
    }
}

extern "C" void kernel_launch(void* const* d_in, const int* in_sizes, int n_in,
                              void* d_out, int out_size) {
    const float* x    = (const float*)d_in[0];
    const float* Wih0 = (const float*)d_in[1];
    const float* Whh0 = (const float*)d_in[2];
    const float* bih0 = (const float*)d_in[3];
    const float* bhh0 = (const float*)d_in[4];
    const float* Wih1 = (const float*)d_in[5];
    const float* Whh1 = (const float*)d_in[6];
    const float* bih1 = (const float*)d_in[7];
    const float* bhh1 = (const float*)d_in[8];
    const float* Wfc  = (const float*)d_in[9];
    const float* bfc  = (const float*)d_in[10];
    float* out = (float*)d_out;

    const size_t smem = (size_t)SM_TOT * sizeof(float);
    cudaFuncSetAttribute(lstm2_fused_kernel,
                         cudaFuncAttributeMaxDynamicSharedMemorySize, (int)smem);
    lstm2_fused_kernel<<<B_TOT / TB, NTH, smem>>>(
        x, Wih0, Whh0, bih0, bhh0, Wih1, Whh1, bih1, bhh1, Wfc, bfc, out);
}